// round 1
// baseline (speedup 1.0000x reference)
#include <cuda_runtime.h>
#include <cuda_bf16.h>
#include <cstdint>

// Shapes (fixed for this problem)
//  x: [2, 2048, 1024]  mask: [1,1,2048,2048] int32
//  W*: [1024,1024], b*: [1024]
//  out: [2, 2048, 1024] fp32
#define BATCH 2
#define SEQ 2048
#define DMODEL 1024
#define NHEADS 16
#define HDIM 64
#define MTOT (BATCH * SEQ)          // 4096

// ---------------------------------------------------------------------------
// Scratch (static device globals — allocation-free per harness rules)
// ---------------------------------------------------------------------------
__device__ float g_Q[BATCH * NHEADS * SEQ * HDIM];   // [B,H,S,Dh] 16 MB
__device__ float g_K[BATCH * NHEADS * SEQ * HDIM];
__device__ float g_V[BATCH * NHEADS * SEQ * HDIM];
__device__ float g_CTX[MTOT * DMODEL];               // [B,S,D]    16 MB

// ---------------------------------------------------------------------------
// SGEMM: C[M,N] = A[M,K] @ B[K,N] + bias[N]
// 128x128 block tile, BK=16, 256 threads, 8x8 per thread (2x2 of float4).
// headSplit==1: write C into [B,H,S,Dh] layout (for Q/K/V).
// ---------------------------------------------------------------------------
#define GBM 128
#define GBN 128
#define GBK 16

__global__ __launch_bounds__(256, 2)
void sgemm_bias(const float* __restrict__ A, const float* __restrict__ B,
                const float* __restrict__ bias, float* __restrict__ C,
                int M, int N, int K, int headSplit)
{
    __shared__ float As[GBK][GBM];   // A tile stored k-major (transposed)
    __shared__ float Bs[GBK][GBN];

    const int tid = threadIdx.x;
    const int tx = tid & 15;
    const int ty = tid >> 4;
    const int bm = blockIdx.y * GBM;
    const int bn = blockIdx.x * GBN;

    float acc[8][8];
    #pragma unroll
    for (int i = 0; i < 8; i++)
        #pragma unroll
        for (int j = 0; j < 8; j++) acc[i][j] = 0.0f;

    for (int k0 = 0; k0 < K; k0 += GBK) {
        // Load A tile: 128x16 = 512 float4 => 2 per thread
        #pragma unroll
        for (int i = 0; i < 2; i++) {
            int lin = tid * 2 + i;               // 0..511
            int r   = lin >> 2;                  // 0..127
            int c4  = (lin & 3) * 4;             // 0,4,8,12
            float4 v = *(const float4*)&A[(size_t)(bm + r) * K + k0 + c4];
            As[c4 + 0][r] = v.x; As[c4 + 1][r] = v.y;
            As[c4 + 2][r] = v.z; As[c4 + 3][r] = v.w;
        }
        // Load B tile: 16x128 = 512 float4 => 2 per thread (coalesced)
        #pragma unroll
        for (int i = 0; i < 2; i++) {
            int lin = tid * 2 + i;
            int r   = lin >> 5;                  // 0..15
            int c4  = (lin & 31) * 4;            // 0..124
            *(float4*)&Bs[r][c4] = *(const float4*)&B[(size_t)(k0 + r) * N + bn + c4];
        }
        __syncthreads();

        #pragma unroll
        for (int k = 0; k < GBK; k++) {
            float ar[8], br[8];
            *(float4*)&ar[0] = *(float4*)&As[k][ty * 4];
            *(float4*)&ar[4] = *(float4*)&As[k][64 + ty * 4];
            *(float4*)&br[0] = *(float4*)&Bs[k][tx * 4];
            *(float4*)&br[4] = *(float4*)&Bs[k][64 + tx * 4];
            #pragma unroll
            for (int i = 0; i < 8; i++)
                #pragma unroll
                for (int j = 0; j < 8; j++)
                    acc[i][j] += ar[i] * br[j];
        }
        __syncthreads();
    }

    // Store with bias
    #pragma unroll
    for (int ih = 0; ih < 2; ih++) {
        #pragma unroll
        for (int r = 0; r < 4; r++) {
            int m = bm + ih * 64 + ty * 4 + r;
            #pragma unroll
            for (int jh = 0; jh < 2; jh++) {
                #pragma unroll
                for (int c = 0; c < 4; c++) {
                    int n = bn + jh * 64 + tx * 4 + c;
                    float val = acc[ih * 4 + r][jh * 4 + c] + bias[n];
                    if (headSplit) {
                        int b = m >> 11;          // m / 2048
                        int s = m & 2047;
                        int h = n >> 6;           // n / 64
                        int d = n & 63;
                        C[((size_t)((b << 4) + h) * SEQ + s) * HDIM + d] = val;
                    } else {
                        C[(size_t)m * N + n] = val;
                    }
                }
            }
        }
    }
}

// ---------------------------------------------------------------------------
// Flash attention: per (b,h), 64 q-rows per block, loop over 32 k-tiles of 64.
// Online softmax, fp32. Context written to [B,S,D].
// ---------------------------------------------------------------------------
#define FPAD 68                     // padded row stride (float4-aligned)
#define FLASH_SMEM (5 * 64 * FPAD * 4)  // Qs,Kst,Vs,Ps (f32) + Ms (int) = 87040 B

__global__ __launch_bounds__(256, 2)
void flash_attn(const float* __restrict__ Q, const float* __restrict__ Kg,
                const float* __restrict__ Vg, const int* __restrict__ mask,
                float* __restrict__ ctx)
{
    extern __shared__ char smem_raw[];
    float* Qs  = (float*)smem_raw;            // [64][FPAD]  row(q)  x d
    float* Kst = Qs  + 64 * FPAD;             // [64][FPAD]  d       x col(k)
    float* Vs  = Kst + 64 * FPAD;             // [64][FPAD]  row(k)  x d
    float* Ps  = Vs  + 64 * FPAD;             // [64][FPAD]  row(q)  x col(k)
    int*   Ms  = (int*)(Ps + 64 * FPAD);      // [64][FPAD]  row(q)  x col(k)

    const int tid = threadIdx.x;
    const int tx = tid & 15;
    const int ty = tid >> 4;
    const int qt = blockIdx.x;                // q tile, 0..31
    const int bh = blockIdx.y;                // b*16+h, 0..31

    const float* Qb = Q  + (size_t)bh * SEQ * HDIM;
    const float* Kb = Kg + (size_t)bh * SEQ * HDIM;
    const float* Vb = Vg + (size_t)bh * SEQ * HDIM;

    // Load Q tile [64 x 64], row-major, padded
    #pragma unroll
    for (int i = 0; i < 4; i++) {
        int lin4 = tid + i * 256;             // 0..1023 float4 units
        int r    = lin4 >> 4;
        int c4   = (lin4 & 15) * 4;
        *(float4*)&Qs[r * FPAD + c4] =
            *(const float4*)&Qb[(size_t)(qt * 64 + r) * HDIM + c4];
    }

    float acc[4][4];
    float mrow[4], lrow[4];
    #pragma unroll
    for (int r = 0; r < 4; r++) {
        mrow[r] = -1e30f; lrow[r] = 0.0f;
        #pragma unroll
        for (int c = 0; c < 4; c++) acc[r][c] = 0.0f;
    }

    const int row0 = ty * 4;

    for (int kt = 0; kt < 32; kt++) {
        __syncthreads();  // previous iter's readers done before overwriting tiles

        // Load K (d-major), V (row-major), mask tile
        #pragma unroll
        for (int i = 0; i < 4; i++) {
            int lin4 = tid + i * 256;
            int j    = lin4 >> 4;             // row within k tile
            int c4   = (lin4 & 15) * 4;       // d offset
            float4 kv = *(const float4*)&Kb[(size_t)(kt * 64 + j) * HDIM + c4];
            Kst[(c4 + 0) * FPAD + j] = kv.x;
            Kst[(c4 + 1) * FPAD + j] = kv.y;
            Kst[(c4 + 2) * FPAD + j] = kv.z;
            Kst[(c4 + 3) * FPAD + j] = kv.w;
            *(float4*)&Vs[j * FPAD + c4] =
                *(const float4*)&Vb[(size_t)(kt * 64 + j) * HDIM + c4];
            *(int4*)&Ms[j * FPAD + c4] =
                *(const int4*)&mask[(size_t)(qt * 64 + j) * SEQ + kt * 64 + c4];
        }
        __syncthreads();

        // Scores: s[r][c] = Q[row] . K[col]
        float s[4][4];
        #pragma unroll
        for (int r = 0; r < 4; r++)
            #pragma unroll
            for (int c = 0; c < 4; c++) s[r][c] = 0.0f;

        #pragma unroll 8
        for (int d = 0; d < 64; d++) {
            float qreg[4], kreg[4];
            #pragma unroll
            for (int r = 0; r < 4; r++) qreg[r] = Qs[(row0 + r) * FPAD + d];
            *(float4*)kreg = *(float4*)&Kst[d * FPAD + tx * 4];
            #pragma unroll
            for (int r = 0; r < 4; r++)
                #pragma unroll
                for (int c = 0; c < 4; c++)
                    s[r][c] += qreg[r] * kreg[c];
        }

        // Scale + mask
        #pragma unroll
        for (int r = 0; r < 4; r++)
            #pragma unroll
            for (int c = 0; c < 4; c++) {
                float v = s[r][c] * 0.125f;   // 1/sqrt(64)
                s[r][c] = (Ms[(row0 + r) * FPAD + tx * 4 + c] == 0) ? -1e9f : v;
            }

        // Online softmax update
        #pragma unroll
        for (int r = 0; r < 4; r++) {
            float mx = fmaxf(fmaxf(s[r][0], s[r][1]), fmaxf(s[r][2], s[r][3]));
            #pragma unroll
            for (int off = 8; off > 0; off >>= 1)
                mx = fmaxf(mx, __shfl_xor_sync(0xffffffffu, mx, off, 16));
            float mnew  = fmaxf(mrow[r], mx);
            float scale = __expf(mrow[r] - mnew);
            mrow[r] = mnew;
            lrow[r] *= scale;
            #pragma unroll
            for (int c = 0; c < 4; c++) acc[r][c] *= scale;
            float psum = 0.0f;
            #pragma unroll
            for (int c = 0; c < 4; c++) {
                float p = __expf(s[r][c] - mnew);
                Ps[(row0 + r) * FPAD + tx * 4 + c] = p;
                psum += p;
            }
            lrow[r] += psum;
        }
        __syncthreads();

        // acc += P @ V
        #pragma unroll 8
        for (int j = 0; j < 64; j++) {
            float preg[4], vreg[4];
            #pragma unroll
            for (int r = 0; r < 4; r++) preg[r] = Ps[(row0 + r) * FPAD + j];
            *(float4*)vreg = *(float4*)&Vs[j * FPAD + tx * 4];
            #pragma unroll
            for (int r = 0; r < 4; r++)
                #pragma unroll
                for (int c = 0; c < 4; c++)
                    acc[r][c] += preg[r] * vreg[c];
        }
    }

    // Finalize: divide by l, write context [B,S,D]
    const int b = bh >> 4;
    const int h = bh & 15;
    #pragma unroll
    for (int r = 0; r < 4; r++) {
        float lt = lrow[r];
        #pragma unroll
        for (int off = 8; off > 0; off >>= 1)
            lt += __shfl_xor_sync(0xffffffffu, lt, off, 16);
        float inv = 1.0f / lt;
        float4 o;
        o.x = acc[r][0] * inv; o.y = acc[r][1] * inv;
        o.z = acc[r][2] * inv; o.w = acc[r][3] * inv;
        int sq = qt * 64 + row0 + r;
        *(float4*)&ctx[(size_t)(b * SEQ + sq) * DMODEL + h * HDIM + tx * 4] = o;
    }
}

// ---------------------------------------------------------------------------
// Launch
// ---------------------------------------------------------------------------
extern "C" void kernel_launch(void* const* d_in, const int* in_sizes, int n_in,
                              void* d_out, int out_size)
{
    const float* x    = (const float*)d_in[0];
    const int*   mask = (const int*)  d_in[1];
    const float* Wq   = (const float*)d_in[2];
    const float* bq   = (const float*)d_in[3];
    const float* Wk   = (const float*)d_in[4];
    const float* bk   = (const float*)d_in[5];
    const float* Wv   = (const float*)d_in[6];
    const float* bv   = (const float*)d_in[7];
    const float* Wo   = (const float*)d_in[8];
    const float* bo   = (const float*)d_in[9];
    float* out = (float*)d_out;

    float *gQ, *gK, *gV, *gC;
    cudaGetSymbolAddress((void**)&gQ, g_Q);
    cudaGetSymbolAddress((void**)&gK, g_K);
    cudaGetSymbolAddress((void**)&gV, g_V);
    cudaGetSymbolAddress((void**)&gC, g_CTX);

    cudaFuncSetAttribute(flash_attn, cudaFuncAttributeMaxDynamicSharedMemorySize,
                         FLASH_SMEM);

    dim3 gemmGrid(DMODEL / GBN, MTOT / GBM);   // (8, 32)
    sgemm_bias<<<gemmGrid, 256>>>(x, Wq, bq, gQ, MTOT, DMODEL, DMODEL, 1);
    sgemm_bias<<<gemmGrid, 256>>>(x, Wk, bk, gK, MTOT, DMODEL, DMODEL, 1);
    sgemm_bias<<<gemmGrid, 256>>>(x, Wv, bv, gV, MTOT, DMODEL, DMODEL, 1);

    flash_attn<<<dim3(SEQ / 64, BATCH * NHEADS), 256, FLASH_SMEM>>>(
        gQ, gK, gV, mask, gC);

    sgemm_bias<<<gemmGrid, 256>>>(gC, Wo, bo, out, MTOT, DMODEL, DMODEL, 0);
}

// round 3
// speedup vs baseline: 1.3372x; 1.3372x over previous
#include <cuda_runtime.h>
#include <cuda_bf16.h>
#include <cstdint>

// Shapes (fixed): x [2,2048,1024], mask [1,1,2048,2048] i32, W* [1024,1024], b* [1024]
#define BATCH 2
#define SEQ 2048
#define DMODEL 1024
#define NHEADS 16
#define HDIM 64
#define MTOT (BATCH * SEQ)          // 4096

// ---------------------------------------------------------------------------
// Scratch (static device globals — allocation-free per harness rules)
// ---------------------------------------------------------------------------
__device__ __align__(16) __nv_bfloat16 g_xh[MTOT * DMODEL];    // x split hi/lo
__device__ __align__(16) __nv_bfloat16 g_xl[MTOT * DMODEL];
__device__ __align__(16) __nv_bfloat16 g_WTh[4][DMODEL * DMODEL];  // W^T splits (q,k,v,o)
__device__ __align__(16) __nv_bfloat16 g_WTl[4][DMODEL * DMODEL];
__device__ __align__(16) float g_Q[BATCH * NHEADS * SEQ * HDIM];   // [B,H,S,Dh] fp32
__device__ __align__(16) float g_K[BATCH * NHEADS * SEQ * HDIM];
__device__ __align__(16) float g_V[BATCH * NHEADS * SEQ * HDIM];
__device__ __align__(16) __nv_bfloat16 g_ctxh[MTOT * DMODEL];  // context split hi/lo
__device__ __align__(16) __nv_bfloat16 g_ctxl[MTOT * DMODEL];

// ---------------------------------------------------------------------------
// MMA helpers (portable: compile at compute_103, run as HMMA on sm_103a)
// ---------------------------------------------------------------------------
__device__ __forceinline__ uint32_t smem_u32(const void* p) {
    uint32_t a;
    asm("{ .reg .u64 t; cvta.to.shared.u64 t, %1; cvt.u32.u64 %0, t; }" : "=r"(a) : "l"(p));
    return a;
}
__device__ __forceinline__ void ldsm_x4(uint32_t* r, uint32_t addr) {
    asm volatile("ldmatrix.sync.aligned.m8n8.x4.shared.b16 {%0,%1,%2,%3}, [%4];"
        : "=r"(r[0]), "=r"(r[1]), "=r"(r[2]), "=r"(r[3]) : "r"(addr));
}
__device__ __forceinline__ void mma_bf16(float* d, const uint32_t* a, const uint32_t* b) {
    asm volatile("mma.sync.aligned.m16n8k16.row.col.f32.bf16.bf16.f32 "
        "{%0,%1,%2,%3}, {%4,%5,%6,%7}, {%8,%9}, {%0,%1,%2,%3};"
        : "+f"(d[0]), "+f"(d[1]), "+f"(d[2]), "+f"(d[3])
        : "r"(a[0]), "r"(a[1]), "r"(a[2]), "r"(a[3]), "r"(b[0]), "r"(b[1]));
}

// ---------------------------------------------------------------------------
// Prep: elementwise fp32 -> bf16 hi/lo split
// ---------------------------------------------------------------------------
__global__ void split_f32(const float* __restrict__ X, __nv_bfloat16* __restrict__ Xh,
                          __nv_bfloat16* __restrict__ Xl, int n)
{
    int i = blockIdx.x * blockDim.x + threadIdx.x;
    if (i < n) {
        float v = X[i];
        __nv_bfloat16 h = __float2bfloat16(v);
        Xh[i] = h;
        Xl[i] = __float2bfloat16(v - __bfloat162float(h));
    }
}

// Prep: W [K,N] -> WT [N,K] bf16 hi/lo
__global__ void transpose_split(const float* __restrict__ W,
                                __nv_bfloat16* __restrict__ Th, __nv_bfloat16* __restrict__ Tl)
{
    __shared__ float t[32][33];
    int bx = blockIdx.x * 32;   // n block
    int by = blockIdx.y * 32;   // k block
    int tx = threadIdx.x, ty = threadIdx.y;  // 32 x 8
    #pragma unroll
    for (int i = 0; i < 4; i++)
        t[ty + i * 8][tx] = W[(size_t)(by + ty + i * 8) * DMODEL + bx + tx];
    __syncthreads();
    #pragma unroll
    for (int i = 0; i < 4; i++) {
        float v = t[tx][ty + i * 8];                        // = W[by+tx][bx+ty+i*8]
        size_t o = (size_t)(bx + ty + i * 8) * DMODEL + by + tx;
        __nv_bfloat16 h = __float2bfloat16(v);
        Th[o] = h;
        Tl[o] = __float2bfloat16(v - __bfloat162float(h));
    }
}

// ---------------------------------------------------------------------------
// HMMA GEMM: C[4096,1024] = A[4096,1024] @ WT[1024,1024]^T + bias
// A, WT given as bf16 hi/lo pairs; 3-term split accumulation in fp32.
// Tile 128x128, K-chunk 32. 256 threads = 8 warps (4m x 2n), warp tile 32x64.
// Smem row stride 40 bf16 (80 B) -> conflict-free ldmatrix.
// headSplit: write [B,H,S,Dh] (QKV) else row-major (O).
// ---------------------------------------------------------------------------
#define KSTRIDE 40                 // bf16 elements per smem row (32 data + 8 pad)

__global__ __launch_bounds__(256)
void mm_mma(const __nv_bfloat16* __restrict__ Ah, const __nv_bfloat16* __restrict__ Al,
            const __nv_bfloat16* __restrict__ Bh, const __nv_bfloat16* __restrict__ Bl,
            const float* __restrict__ bias, float* __restrict__ C, int headSplit)
{
    __shared__ __nv_bfloat16 sAh[128 * KSTRIDE];
    __shared__ __nv_bfloat16 sAl[128 * KSTRIDE];
    __shared__ __nv_bfloat16 sBh[128 * KSTRIDE];
    __shared__ __nv_bfloat16 sBl[128 * KSTRIDE];

    const int tid = threadIdx.x;
    const int wid = tid >> 5;
    const int lane = tid & 31;
    const int wm = wid & 3;            // warp m index (0..3) -> rows wm*32
    const int wn = wid >> 2;           // warp n index (0..1) -> cols wn*64
    const int bm = blockIdx.y * 128;
    const int bn = blockIdx.x * 128;

    const uint32_t uAh = smem_u32(sAh), uAl = smem_u32(sAl);
    const uint32_t uBh = smem_u32(sBh), uBl = smem_u32(sBl);

    float acc[2][8][4];
    #pragma unroll
    for (int mi = 0; mi < 2; mi++)
        #pragma unroll
        for (int ni = 0; ni < 8; ni++)
            #pragma unroll
            for (int e = 0; e < 4; e++) acc[mi][ni][e] = 0.0f;

    // Per-thread staging addresses: 2 units of 16B per tile per chunk
    // lin = tid + u*256 (0..511): row = lin>>2, seg = lin&3 (16B within 64B row)
    int rowA[2], segA[2];
    #pragma unroll
    for (int u = 0; u < 2; u++) { int lin = tid + u * 256; rowA[u] = lin >> 2; segA[u] = lin & 3; }

    uint4 stA[2], stAl[2], stB[2], stBl[2];

    // Prefetch chunk 0
    #pragma unroll
    for (int u = 0; u < 2; u++) {
        size_t ga = (size_t)(bm + rowA[u]) * DMODEL + segA[u] * 8;
        size_t gb = (size_t)(bn + rowA[u]) * DMODEL + segA[u] * 8;
        stA[u]  = *(const uint4*)(Ah + ga);
        stAl[u] = *(const uint4*)(Al + ga);
        stB[u]  = *(const uint4*)(Bh + gb);
        stBl[u] = *(const uint4*)(Bl + gb);
    }

    // ldmatrix source addresses (byte offsets into smem, bf16 stride KSTRIDE)
    // A: row = wm*32 + mi*16 + (lane&15), k = s*16 + (lane>>4)*8
    // B: row(n) = wn*64 + g*16 + ((lane>>4)&1)*8 + (lane&7), k = s*16 + ((lane>>3)&1)*8
    const int aRow = wm * 32 + (lane & 15);
    const int aK   = (lane >> 4) * 8;
    const int bRow = wn * 64 + ((lane >> 4) & 1) * 8 + (lane & 7);
    const int bK   = ((lane >> 3) & 1) * 8;

    for (int c = 0; c < DMODEL / 32; c++) {
        __syncthreads();
        #pragma unroll
        for (int u = 0; u < 2; u++) {
            uint32_t so = rowA[u] * KSTRIDE + segA[u] * 8;   // bf16 index
            *(uint4*)(sAh + so) = stA[u];
            *(uint4*)(sAl + so) = stAl[u];
            *(uint4*)(sBh + so) = stB[u];
            *(uint4*)(sBl + so) = stBl[u];
        }
        __syncthreads();

        // Prefetch next chunk while computing this one
        if (c + 1 < DMODEL / 32) {
            const int k0 = (c + 1) * 32;
            #pragma unroll
            for (int u = 0; u < 2; u++) {
                size_t ga = (size_t)(bm + rowA[u]) * DMODEL + k0 + segA[u] * 8;
                size_t gb = (size_t)(bn + rowA[u]) * DMODEL + k0 + segA[u] * 8;
                stA[u]  = *(const uint4*)(Ah + ga);
                stAl[u] = *(const uint4*)(Al + ga);
                stB[u]  = *(const uint4*)(Bh + gb);
                stBl[u] = *(const uint4*)(Bl + gb);
            }
        }

        #pragma unroll
        for (int s = 0; s < 2; s++) {
            uint32_t aH[2][4], aL[2][4];
            #pragma unroll
            for (int mi = 0; mi < 2; mi++) {
                uint32_t off = ((aRow + mi * 16) * KSTRIDE + s * 16 + aK) * 2;
                ldsm_x4(aH[mi], uAh + off);
                ldsm_x4(aL[mi], uAl + off);
            }
            uint32_t bH[8][2], bL[8][2];
            #pragma unroll
            for (int g = 0; g < 4; g++) {
                uint32_t off = ((bRow + g * 16) * KSTRIDE + s * 16 + bK) * 2;
                uint32_t r[4], rl[4];
                ldsm_x4(r,  uBh + off);
                ldsm_x4(rl, uBl + off);
                bH[g * 2][0] = r[0];  bH[g * 2][1] = r[1];
                bH[g * 2 + 1][0] = r[2]; bH[g * 2 + 1][1] = r[3];
                bL[g * 2][0] = rl[0]; bL[g * 2][1] = rl[1];
                bL[g * 2 + 1][0] = rl[2]; bL[g * 2 + 1][1] = rl[3];
            }
            #pragma unroll
            for (int mi = 0; mi < 2; mi++)
                #pragma unroll
                for (int ni = 0; ni < 8; ni++) {
                    mma_bf16(acc[mi][ni], aH[mi], bH[ni]);
                    mma_bf16(acc[mi][ni], aH[mi], bL[ni]);
                    mma_bf16(acc[mi][ni], aL[mi], bH[ni]);
                }
        }
    }

    // Epilogue: d0,d1 -> (row, col..col+1); d2,d3 -> (row+8, col..col+1)
    const int rBase = bm + wm * 32 + (lane >> 2);
    const int cBase = bn + wn * 64 + (lane & 3) * 2;
    #pragma unroll
    for (int mi = 0; mi < 2; mi++) {
        #pragma unroll
        for (int ni = 0; ni < 8; ni++) {
            int col = cBase + ni * 8;
            float b0 = bias[col], b1 = bias[col + 1];
            #pragma unroll
            for (int half = 0; half < 2; half++) {
                int m = rBase + mi * 16 + half * 8;
                float v0 = acc[mi][ni][half * 2 + 0] + b0;
                float v1 = acc[mi][ni][half * 2 + 1] + b1;
                if (headSplit) {
                    int b = m >> 11, s = m & 2047;
                    int h = col >> 6, d = col & 63;
                    float* dst = C + ((size_t)((b << 4) + h) * SEQ + s) * HDIM + d;
                    dst[0] = v0; dst[1] = v1;
                } else {
                    float* dst = C + (size_t)m * DMODEL + col;
                    dst[0] = v0; dst[1] = v1;
                }
            }
        }
    }
}

// ---------------------------------------------------------------------------
// Flash attention (fp32 SIMT): 64 q-rows/block, 32 k-tiles of 64.
// Output: context split to bf16 hi/lo in [B,S,D] layout.
// ---------------------------------------------------------------------------
#define FPAD 68
#define FLASH_SMEM (5 * 64 * FPAD * 4)

__global__ __launch_bounds__(256, 2)
void flash_attn(const float* __restrict__ Q, const float* __restrict__ Kg,
                const float* __restrict__ Vg, const int* __restrict__ mask,
                __nv_bfloat16* __restrict__ ctxh, __nv_bfloat16* __restrict__ ctxl)
{
    extern __shared__ char smem_raw[];
    float* Qs  = (float*)smem_raw;
    float* Kst = Qs  + 64 * FPAD;
    float* Vs  = Kst + 64 * FPAD;
    float* Ps  = Vs  + 64 * FPAD;
    int*   Ms  = (int*)(Ps + 64 * FPAD);

    const int tid = threadIdx.x;
    const int tx = tid & 15;
    const int ty = tid >> 4;
    const int qt = blockIdx.x;
    const int bh = blockIdx.y;

    const float* Qb = Q  + (size_t)bh * SEQ * HDIM;
    const float* Kb = Kg + (size_t)bh * SEQ * HDIM;
    const float* Vb = Vg + (size_t)bh * SEQ * HDIM;

    #pragma unroll
    for (int i = 0; i < 4; i++) {
        int lin4 = tid + i * 256;
        int r    = lin4 >> 4;
        int c4   = (lin4 & 15) * 4;
        *(float4*)&Qs[r * FPAD + c4] = *(const float4*)&Qb[(size_t)(qt * 64 + r) * HDIM + c4];
    }

    float acc[4][4];
    float mrow[4], lrow[4];
    #pragma unroll
    for (int r = 0; r < 4; r++) {
        mrow[r] = -1e30f; lrow[r] = 0.0f;
        #pragma unroll
        for (int c = 0; c < 4; c++) acc[r][c] = 0.0f;
    }

    const int row0 = ty * 4;

    for (int kt = 0; kt < 32; kt++) {
        __syncthreads();
        #pragma unroll
        for (int i = 0; i < 4; i++) {
            int lin4 = tid + i * 256;
            int j    = lin4 >> 4;
            int c4   = (lin4 & 15) * 4;
            float4 kv = *(const float4*)&Kb[(size_t)(kt * 64 + j) * HDIM + c4];
            Kst[(c4 + 0) * FPAD + j] = kv.x;
            Kst[(c4 + 1) * FPAD + j] = kv.y;
            Kst[(c4 + 2) * FPAD + j] = kv.z;
            Kst[(c4 + 3) * FPAD + j] = kv.w;
            *(float4*)&Vs[j * FPAD + c4] = *(const float4*)&Vb[(size_t)(kt * 64 + j) * HDIM + c4];
            *(int4*)&Ms[j * FPAD + c4]  = *(const int4*)&mask[(size_t)(qt * 64 + j) * SEQ + kt * 64 + c4];
        }
        __syncthreads();

        float s[4][4];
        #pragma unroll
        for (int r = 0; r < 4; r++)
            #pragma unroll
            for (int c = 0; c < 4; c++) s[r][c] = 0.0f;

        #pragma unroll 8
        for (int d = 0; d < 64; d++) {
            float qreg[4], kreg[4];
            #pragma unroll
            for (int r = 0; r < 4; r++) qreg[r] = Qs[(row0 + r) * FPAD + d];
            *(float4*)kreg = *(float4*)&Kst[d * FPAD + tx * 4];
            #pragma unroll
            for (int r = 0; r < 4; r++)
                #pragma unroll
                for (int c = 0; c < 4; c++)
                    s[r][c] += qreg[r] * kreg[c];
        }

        #pragma unroll
        for (int r = 0; r < 4; r++)
            #pragma unroll
            for (int c = 0; c < 4; c++) {
                float v = s[r][c] * 0.125f;
                s[r][c] = (Ms[(row0 + r) * FPAD + tx * 4 + c] == 0) ? -1e9f : v;
            }

        #pragma unroll
        for (int r = 0; r < 4; r++) {
            float mx = fmaxf(fmaxf(s[r][0], s[r][1]), fmaxf(s[r][2], s[r][3]));
            #pragma unroll
            for (int off = 8; off > 0; off >>= 1)
                mx = fmaxf(mx, __shfl_xor_sync(0xffffffffu, mx, off, 16));
            float mnew  = fmaxf(mrow[r], mx);
            float scale = __expf(mrow[r] - mnew);
            mrow[r] = mnew;
            lrow[r] *= scale;
            #pragma unroll
            for (int c = 0; c < 4; c++) acc[r][c] *= scale;
            float psum = 0.0f;
            #pragma unroll
            for (int c = 0; c < 4; c++) {
                float p = __expf(s[r][c] - mnew);
                Ps[(row0 + r) * FPAD + tx * 4 + c] = p;
                psum += p;
            }
            lrow[r] += psum;
        }
        __syncthreads();

        #pragma unroll 8
        for (int j = 0; j < 64; j++) {
            float preg[4], vreg[4];
            #pragma unroll
            for (int r = 0; r < 4; r++) preg[r] = Ps[(row0 + r) * FPAD + j];
            *(float4*)vreg = *(float4*)&Vs[j * FPAD + tx * 4];
            #pragma unroll
            for (int r = 0; r < 4; r++)
                #pragma unroll
                for (int c = 0; c < 4; c++)
                    acc[r][c] += preg[r] * vreg[c];
        }
    }

    const int b = bh >> 4;
    const int h = bh & 15;
    #pragma unroll
    for (int r = 0; r < 4; r++) {
        float lt = lrow[r];
        #pragma unroll
        for (int off = 8; off > 0; off >>= 1)
            lt += __shfl_xor_sync(0xffffffffu, lt, off, 16);
        float inv = 1.0f / lt;
        float o[4];
        #pragma unroll
        for (int c = 0; c < 4; c++) o[c] = acc[r][c] * inv;
        int sq = qt * 64 + row0 + r;
        size_t base = (size_t)(b * SEQ + sq) * DMODEL + h * HDIM + tx * 4;
        __nv_bfloat16 hh[4], ll[4];
        #pragma unroll
        for (int c = 0; c < 4; c++) {
            hh[c] = __float2bfloat16(o[c]);
            ll[c] = __float2bfloat16(o[c] - __bfloat162float(hh[c]));
        }
        *(__nv_bfloat162*)&ctxh[base]     = __halves2bfloat162(hh[0], hh[1]);
        *(__nv_bfloat162*)&ctxh[base + 2] = __halves2bfloat162(hh[2], hh[3]);
        *(__nv_bfloat162*)&ctxl[base]     = __halves2bfloat162(ll[0], ll[1]);
        *(__nv_bfloat162*)&ctxl[base + 2] = __halves2bfloat162(ll[2], ll[3]);
    }
}

// ---------------------------------------------------------------------------
// Launch
// ---------------------------------------------------------------------------
extern "C" void kernel_launch(void* const* d_in, const int* in_sizes, int n_in,
                              void* d_out, int out_size)
{
    const float* x    = (const float*)d_in[0];
    const int*   mask = (const int*)  d_in[1];
    const float* W[4] = { (const float*)d_in[2], (const float*)d_in[4],
                          (const float*)d_in[6], (const float*)d_in[8] };   // q,k,v,o
    const float* bq   = (const float*)d_in[3];
    const float* bk   = (const float*)d_in[5];
    const float* bv   = (const float*)d_in[7];
    const float* bo   = (const float*)d_in[9];
    float* out = (float*)d_out;

    __nv_bfloat16 *xh, *xl, *wth, *wtl, *cxh, *cxl;
    float *gQ, *gK, *gV;
    cudaGetSymbolAddress((void**)&xh,  g_xh);
    cudaGetSymbolAddress((void**)&xl,  g_xl);
    cudaGetSymbolAddress((void**)&wth, g_WTh);
    cudaGetSymbolAddress((void**)&wtl, g_WTl);
    cudaGetSymbolAddress((void**)&gQ,  g_Q);
    cudaGetSymbolAddress((void**)&gK,  g_K);
    cudaGetSymbolAddress((void**)&gV,  g_V);
    cudaGetSymbolAddress((void**)&cxh, g_ctxh);
    cudaGetSymbolAddress((void**)&cxl, g_ctxl);

    cudaFuncSetAttribute(flash_attn, cudaFuncAttributeMaxDynamicSharedMemorySize, FLASH_SMEM);

    split_f32<<<(MTOT * DMODEL) / 256, 256>>>(x, xh, xl, MTOT * DMODEL);
    for (int i = 0; i < 4; i++)
        transpose_split<<<dim3(32, 32), dim3(32, 8)>>>(W[i],
            wth + (size_t)i * DMODEL * DMODEL, wtl + (size_t)i * DMODEL * DMODEL);

    dim3 mmGrid(DMODEL / 128, MTOT / 128);   // (8, 32)
    mm_mma<<<mmGrid, 256>>>(xh, xl, wth + 0 * (size_t)DMODEL * DMODEL,
                            wtl + 0 * (size_t)DMODEL * DMODEL, bq, gQ, 1);
    mm_mma<<<mmGrid, 256>>>(xh, xl, wth + 1 * (size_t)DMODEL * DMODEL,
                            wtl + 1 * (size_t)DMODEL * DMODEL, bk, gK, 1);
    mm_mma<<<mmGrid, 256>>>(xh, xl, wth + 2 * (size_t)DMODEL * DMODEL,
                            wtl + 2 * (size_t)DMODEL * DMODEL, bv, gV, 1);

    flash_attn<<<dim3(SEQ / 64, BATCH * NHEADS), 256, FLASH_SMEM>>>(gQ, gK, gV, mask, cxh, cxl);

    mm_mma<<<mmGrid, 256>>>(cxh, cxl, wth + 3 * (size_t)DMODEL * DMODEL,
                            wtl + 3 * (size_t)DMODEL * DMODEL, bo, out, 0);
}

// round 4
// speedup vs baseline: 2.3371x; 1.7477x over previous
#include <cuda_runtime.h>
#include <cuda_bf16.h>
#include <cstdint>

#define BATCH 2
#define SEQ 2048
#define DMODEL 1024
#define NHEADS 16
#define HDIM 64
#define MTOT (BATCH * SEQ)          // 4096

// ---------------------------------------------------------------------------
// Scratch (static device globals)
// ---------------------------------------------------------------------------
__device__ __align__(16) __nv_bfloat16 g_xh[MTOT * DMODEL];
__device__ __align__(16) __nv_bfloat16 g_xl[MTOT * DMODEL];
__device__ __align__(16) __nv_bfloat16 g_WTh[4][DMODEL * DMODEL];
__device__ __align__(16) __nv_bfloat16 g_WTl[4][DMODEL * DMODEL];
__device__ __align__(16) __nv_bfloat16 g_Qh[BATCH * NHEADS * SEQ * HDIM];  // [B,H,S,Dh]
__device__ __align__(16) __nv_bfloat16 g_Ql[BATCH * NHEADS * SEQ * HDIM];
__device__ __align__(16) __nv_bfloat16 g_Kh[BATCH * NHEADS * SEQ * HDIM];
__device__ __align__(16) __nv_bfloat16 g_Kl[BATCH * NHEADS * SEQ * HDIM];
__device__ __align__(16) __nv_bfloat16 g_Vh[BATCH * NHEADS * SEQ * HDIM];
__device__ __align__(16) __nv_bfloat16 g_Vl[BATCH * NHEADS * SEQ * HDIM];
__device__ __align__(16) __nv_bfloat16 g_ctxh[MTOT * DMODEL];
__device__ __align__(16) __nv_bfloat16 g_ctxl[MTOT * DMODEL];

// ---------------------------------------------------------------------------
// MMA / async helpers (portable PTX, compiles at compute_103)
// ---------------------------------------------------------------------------
__device__ __forceinline__ uint32_t smem_u32(const void* p) {
    uint32_t a;
    asm("{ .reg .u64 t; cvta.to.shared.u64 t, %1; cvt.u32.u64 %0, t; }" : "=r"(a) : "l"(p));
    return a;
}
__device__ __forceinline__ void ldsm_x4(uint32_t* r, uint32_t addr) {
    asm volatile("ldmatrix.sync.aligned.m8n8.x4.shared.b16 {%0,%1,%2,%3}, [%4];"
        : "=r"(r[0]), "=r"(r[1]), "=r"(r[2]), "=r"(r[3]) : "r"(addr));
}
__device__ __forceinline__ void ldsm_x4_t(uint32_t* r, uint32_t addr) {
    asm volatile("ldmatrix.sync.aligned.m8n8.x4.trans.shared.b16 {%0,%1,%2,%3}, [%4];"
        : "=r"(r[0]), "=r"(r[1]), "=r"(r[2]), "=r"(r[3]) : "r"(addr));
}
__device__ __forceinline__ void mma_bf16(float* d, const uint32_t* a, const uint32_t* b) {
    asm volatile("mma.sync.aligned.m16n8k16.row.col.f32.bf16.bf16.f32 "
        "{%0,%1,%2,%3}, {%4,%5,%6,%7}, {%8,%9}, {%0,%1,%2,%3};"
        : "+f"(d[0]), "+f"(d[1]), "+f"(d[2]), "+f"(d[3])
        : "r"(a[0]), "r"(a[1]), "r"(a[2]), "r"(a[3]), "r"(b[0]), "r"(b[1]));
}
#define CP_ASYNC16(dst_u32, src_gptr) \
    asm volatile("cp.async.cg.shared.global [%0], [%1], 16;" \
        :: "r"(dst_u32), "l"(__cvta_generic_to_global(src_gptr)) : "memory")
#define CP_COMMIT() asm volatile("cp.async.commit_group;" ::: "memory")
#define CP_WAIT1()  asm volatile("cp.async.wait_group 1;" ::: "memory")
#define CP_WAIT0()  asm volatile("cp.async.wait_group 0;" ::: "memory")

// ---------------------------------------------------------------------------
// Prep kernels
// ---------------------------------------------------------------------------
__global__ void split_f32(const float* __restrict__ X, __nv_bfloat16* __restrict__ Xh,
                          __nv_bfloat16* __restrict__ Xl, int n)
{
    int i = blockIdx.x * blockDim.x + threadIdx.x;
    if (i < n) {
        float v = X[i];
        __nv_bfloat16 h = __float2bfloat16(v);
        Xh[i] = h;
        Xl[i] = __float2bfloat16(v - __bfloat162float(h));
    }
}

__global__ void transpose_split(const float* __restrict__ W,
                                __nv_bfloat16* __restrict__ Th, __nv_bfloat16* __restrict__ Tl)
{
    __shared__ float t[32][33];
    int bx = blockIdx.x * 32;
    int by = blockIdx.y * 32;
    int tx = threadIdx.x, ty = threadIdx.y;
    #pragma unroll
    for (int i = 0; i < 4; i++)
        t[ty + i * 8][tx] = W[(size_t)(by + ty + i * 8) * DMODEL + bx + tx];
    __syncthreads();
    #pragma unroll
    for (int i = 0; i < 4; i++) {
        float v = t[tx][ty + i * 8];
        size_t o = (size_t)(bx + ty + i * 8) * DMODEL + by + tx;
        __nv_bfloat16 h = __float2bfloat16(v);
        Th[o] = h;
        Tl[o] = __float2bfloat16(v - __bfloat162float(h));
    }
}

// ---------------------------------------------------------------------------
// HMMA GEMM (3-term split). headSplit=1: bf16 hi/lo out in [B,H,S,Dh].
// headSplit=0: fp32 out row-major.
// ---------------------------------------------------------------------------
#define KSTRIDE 40

__global__ __launch_bounds__(256)
void mm_mma(const __nv_bfloat16* __restrict__ Ah, const __nv_bfloat16* __restrict__ Al,
            const __nv_bfloat16* __restrict__ Bh, const __nv_bfloat16* __restrict__ Bl,
            const float* __restrict__ bias, float* __restrict__ Cf,
            __nv_bfloat16* __restrict__ Ch, __nv_bfloat16* __restrict__ Cl, int headSplit)
{
    __shared__ __nv_bfloat16 sAh[128 * KSTRIDE];
    __shared__ __nv_bfloat16 sAl[128 * KSTRIDE];
    __shared__ __nv_bfloat16 sBh[128 * KSTRIDE];
    __shared__ __nv_bfloat16 sBl[128 * KSTRIDE];

    const int tid = threadIdx.x;
    const int wid = tid >> 5;
    const int lane = tid & 31;
    const int wm = wid & 3;
    const int wn = wid >> 2;
    const int bm = blockIdx.y * 128;
    const int bn = blockIdx.x * 128;

    const uint32_t uAh = smem_u32(sAh), uAl = smem_u32(sAl);
    const uint32_t uBh = smem_u32(sBh), uBl = smem_u32(sBl);

    float acc[2][8][4];
    #pragma unroll
    for (int mi = 0; mi < 2; mi++)
        #pragma unroll
        for (int ni = 0; ni < 8; ni++)
            #pragma unroll
            for (int e = 0; e < 4; e++) acc[mi][ni][e] = 0.0f;

    int rowA[2], segA[2];
    #pragma unroll
    for (int u = 0; u < 2; u++) { int lin = tid + u * 256; rowA[u] = lin >> 2; segA[u] = lin & 3; }

    uint4 stA[2], stAl[2], stB[2], stBl[2];
    #pragma unroll
    for (int u = 0; u < 2; u++) {
        size_t ga = (size_t)(bm + rowA[u]) * DMODEL + segA[u] * 8;
        size_t gb = (size_t)(bn + rowA[u]) * DMODEL + segA[u] * 8;
        stA[u]  = *(const uint4*)(Ah + ga);
        stAl[u] = *(const uint4*)(Al + ga);
        stB[u]  = *(const uint4*)(Bh + gb);
        stBl[u] = *(const uint4*)(Bl + gb);
    }

    const int aRow = wm * 32 + (lane & 15);
    const int aK   = (lane >> 4) * 8;
    const int bRow = wn * 64 + ((lane >> 4) & 1) * 8 + (lane & 7);
    const int bK   = ((lane >> 3) & 1) * 8;

    for (int c = 0; c < DMODEL / 32; c++) {
        __syncthreads();
        #pragma unroll
        for (int u = 0; u < 2; u++) {
            uint32_t so = rowA[u] * KSTRIDE + segA[u] * 8;
            *(uint4*)(sAh + so) = stA[u];
            *(uint4*)(sAl + so) = stAl[u];
            *(uint4*)(sBh + so) = stB[u];
            *(uint4*)(sBl + so) = stBl[u];
        }
        __syncthreads();

        if (c + 1 < DMODEL / 32) {
            const int k0 = (c + 1) * 32;
            #pragma unroll
            for (int u = 0; u < 2; u++) {
                size_t ga = (size_t)(bm + rowA[u]) * DMODEL + k0 + segA[u] * 8;
                size_t gb = (size_t)(bn + rowA[u]) * DMODEL + k0 + segA[u] * 8;
                stA[u]  = *(const uint4*)(Ah + ga);
                stAl[u] = *(const uint4*)(Al + ga);
                stB[u]  = *(const uint4*)(Bh + gb);
                stBl[u] = *(const uint4*)(Bl + gb);
            }
        }

        #pragma unroll
        for (int s = 0; s < 2; s++) {
            uint32_t aH[2][4], aL[2][4];
            #pragma unroll
            for (int mi = 0; mi < 2; mi++) {
                uint32_t off = ((aRow + mi * 16) * KSTRIDE + s * 16 + aK) * 2;
                ldsm_x4(aH[mi], uAh + off);
                ldsm_x4(aL[mi], uAl + off);
            }
            uint32_t bH[8][2], bL[8][2];
            #pragma unroll
            for (int g = 0; g < 4; g++) {
                uint32_t off = ((bRow + g * 16) * KSTRIDE + s * 16 + bK) * 2;
                uint32_t r[4], rl[4];
                ldsm_x4(r,  uBh + off);
                ldsm_x4(rl, uBl + off);
                bH[g * 2][0] = r[0];  bH[g * 2][1] = r[1];
                bH[g * 2 + 1][0] = r[2]; bH[g * 2 + 1][1] = r[3];
                bL[g * 2][0] = rl[0]; bL[g * 2][1] = rl[1];
                bL[g * 2 + 1][0] = rl[2]; bL[g * 2 + 1][1] = rl[3];
            }
            #pragma unroll
            for (int mi = 0; mi < 2; mi++)
                #pragma unroll
                for (int ni = 0; ni < 8; ni++) {
                    mma_bf16(acc[mi][ni], aH[mi], bH[ni]);
                    mma_bf16(acc[mi][ni], aH[mi], bL[ni]);
                    mma_bf16(acc[mi][ni], aL[mi], bH[ni]);
                }
        }
    }

    const int rBase = bm + wm * 32 + (lane >> 2);
    const int cBase = bn + wn * 64 + (lane & 3) * 2;
    #pragma unroll
    for (int mi = 0; mi < 2; mi++) {
        #pragma unroll
        for (int ni = 0; ni < 8; ni++) {
            int col = cBase + ni * 8;
            float b0 = bias[col], b1 = bias[col + 1];
            #pragma unroll
            for (int half = 0; half < 2; half++) {
                int m = rBase + mi * 16 + half * 8;
                float v0 = acc[mi][ni][half * 2 + 0] + b0;
                float v1 = acc[mi][ni][half * 2 + 1] + b1;
                if (headSplit) {
                    int b = m >> 11, s = m & 2047;
                    int h = col >> 6, d = col & 63;
                    size_t o = ((size_t)((b << 4) + h) * SEQ + s) * HDIM + d;
                    __nv_bfloat16 h0 = __float2bfloat16(v0);
                    __nv_bfloat16 h1 = __float2bfloat16(v1);
                    __nv_bfloat16 l0 = __float2bfloat16(v0 - __bfloat162float(h0));
                    __nv_bfloat16 l1 = __float2bfloat16(v1 - __bfloat162float(h1));
                    *(__nv_bfloat162*)(Ch + o) = __halves2bfloat162(h0, h1);
                    *(__nv_bfloat162*)(Cl + o) = __halves2bfloat162(l0, l1);
                } else {
                    float* dst = Cf + (size_t)m * DMODEL + col;
                    dst[0] = v0; dst[1] = v1;
                }
            }
        }
    }
}

// ---------------------------------------------------------------------------
// Flash attention on HMMA: 128 q-rows per CTA (8 warps x 16 rows),
// k-tiles of 64, double-buffered via cp.async. 3-term bf16 split for
// both Q*K^T and P*V. Softmax fp32 in registers.
// ---------------------------------------------------------------------------
#define FSTR 72                     // bf16 per smem row (64 data + 8 pad)
#define FROWB (FSTR * 2)            // 144 bytes
#define FQ_BYTES (128 * FSTR * 2)   // 18432 per Q split
#define FT_BYTES (64 * FSTR * 2)    // 9216 per K/V tile
#define FSTAGE_BYTES (4 * FT_BYTES) // Kh,Kl,Vh,Vl
#define FLASH_SMEM (2 * FQ_BYTES + 2 * FSTAGE_BYTES)  // 110592

__global__ __launch_bounds__(256, 1)
void flash_mma(const __nv_bfloat16* __restrict__ Qh, const __nv_bfloat16* __restrict__ Ql,
               const __nv_bfloat16* __restrict__ Kh, const __nv_bfloat16* __restrict__ Kl,
               const __nv_bfloat16* __restrict__ Vh, const __nv_bfloat16* __restrict__ Vl,
               const int* __restrict__ mask,
               __nv_bfloat16* __restrict__ ctxh, __nv_bfloat16* __restrict__ ctxl)
{
    extern __shared__ char sm[];
    __nv_bfloat16* sQh = (__nv_bfloat16*)sm;
    __nv_bfloat16* sQl = sQh + 128 * FSTR;
    char* sKV = sm + 2 * FQ_BYTES;

    const int tid = threadIdx.x;
    const int lane = tid & 31;
    const int w = tid >> 5;
    const int qt = blockIdx.x;          // 0..15 (128-row q tiles)
    const int bh = blockIdx.y;          // 0..31
    const size_t base = (size_t)bh * SEQ * HDIM;

    // Load Q tile (128 x 64) hi/lo
    #pragma unroll
    for (int i = 0; i < 4; i++) {
        int lin = tid + i * 256;         // 0..1023 : 128 rows x 8 segs
        int r = lin >> 3, c = lin & 7;
        *(uint4*)&sQh[r * FSTR + c * 8] = *(const uint4*)&Qh[base + (size_t)(qt * 128 + r) * HDIM + c * 8];
        *(uint4*)&sQl[r * FSTR + c * 8] = *(const uint4*)&Ql[base + (size_t)(qt * 128 + r) * HDIM + c * 8];
    }

    const uint32_t uKV = smem_u32(sKV);
    const __nv_bfloat16* srcs[4] = { Kh, Kl, Vh, Vl };

    // async issue of one k-tile into a stage
    auto issue = [&](int kt, int stage) {
        #pragma unroll
        for (int t = 0; t < 4; t++) {
            #pragma unroll
            for (int u = 0; u < 2; u++) {
                int lin = tid * 2 + u;          // 0..511 : 64 rows x 8 segs
                int r = lin >> 3, c = lin & 7;
                uint32_t dst = uKV + (stage * 4 + t) * FT_BYTES + r * FROWB + c * 16;
                const __nv_bfloat16* src = srcs[t] + base + (size_t)(kt * 64 + r) * HDIM + c * 8;
                CP_ASYNC16(dst, src);
            }
        }
        CP_COMMIT();
    };

    issue(0, 0);
    issue(1, 1);

    __syncthreads();   // Q smem visible

    // Q fragments (register resident): 4 k-chunks x hi/lo
    uint32_t qhf[4][4], qlf[4][4];
    const uint32_t uQh = smem_u32(sQh), uQl = smem_u32(sQl);
    #pragma unroll
    for (int kch = 0; kch < 4; kch++) {
        uint32_t off = (w * 16 + (lane & 15)) * FROWB + (kch * 16 + (lane >> 4) * 8) * 2;
        ldsm_x4(qhf[kch], uQh + off);
        ldsm_x4(qlf[kch], uQl + off);
    }

    float O[8][4];
    #pragma unroll
    for (int j = 0; j < 8; j++)
        #pragma unroll
        for (int e = 0; e < 4; e++) O[j][e] = 0.0f;
    float m0 = -1e30f, m1 = -1e30f, l0 = 0.0f, l1 = 0.0f;

    const int q0 = qt * 128 + w * 16 + (lane >> 2);   // global q row (and +8)
    const int colOff = 2 * (lane & 3);

    for (int kt = 0; kt < 32; kt++) {
        const int stage = kt & 1;
        if (kt + 1 < 32) { CP_WAIT1(); } else { CP_WAIT0(); }
        __syncthreads();

        const uint32_t uKh_ = uKV + (stage * 4 + 0) * FT_BYTES;
        const uint32_t uKl_ = uKV + (stage * 4 + 1) * FT_BYTES;
        const uint32_t uVh_ = uKV + (stage * 4 + 2) * FT_BYTES;
        const uint32_t uVl_ = uKV + (stage * 4 + 3) * FT_BYTES;

        // --- scores S = Q . K^T (3-term split) ---
        float S[8][4];
        #pragma unroll
        for (int j = 0; j < 8; j++)
            #pragma unroll
            for (int e = 0; e < 4; e++) S[j][e] = 0.0f;

        const int rowN = ((lane >> 4) & 1) * 8 + (lane & 7);
        const int bKo  = ((lane >> 3) & 1) * 16;    // byte offset of k-half
        #pragma unroll
        for (int g = 0; g < 4; g++) {
            #pragma unroll
            for (int kch = 0; kch < 4; kch++) {
                uint32_t off = (g * 16 + rowN) * FROWB + kch * 32 + bKo;
                uint32_t bh_[4], bl_[4];
                ldsm_x4(bh_, uKh_ + off);
                ldsm_x4(bl_, uKl_ + off);
                mma_bf16(S[2 * g],     qhf[kch], bh_);
                mma_bf16(S[2 * g + 1], qhf[kch], bh_ + 2);
                mma_bf16(S[2 * g],     qhf[kch], bl_);
                mma_bf16(S[2 * g + 1], qhf[kch], bl_ + 2);
                mma_bf16(S[2 * g],     qlf[kch], bh_);
                mma_bf16(S[2 * g + 1], qlf[kch], bh_ + 2);
            }
        }

        // --- scale + mask ---
        #pragma unroll
        for (int j = 0; j < 8; j++) {
            int kc = kt * 64 + j * 8 + colOff;
            int2 mA = *(const int2*)&mask[(size_t)q0 * SEQ + kc];
            int2 mB = *(const int2*)&mask[(size_t)(q0 + 8) * SEQ + kc];
            S[j][0] = mA.x ? S[j][0] * 0.125f : -1e9f;
            S[j][1] = mA.y ? S[j][1] * 0.125f : -1e9f;
            S[j][2] = mB.x ? S[j][2] * 0.125f : -1e9f;
            S[j][3] = mB.y ? S[j][3] * 0.125f : -1e9f;
        }

        // --- online softmax (rows r and r+8) ---
        float mx0 = -1e30f, mx1 = -1e30f;
        #pragma unroll
        for (int j = 0; j < 8; j++) {
            mx0 = fmaxf(mx0, fmaxf(S[j][0], S[j][1]));
            mx1 = fmaxf(mx1, fmaxf(S[j][2], S[j][3]));
        }
        mx0 = fmaxf(mx0, __shfl_xor_sync(0xffffffffu, mx0, 1));
        mx0 = fmaxf(mx0, __shfl_xor_sync(0xffffffffu, mx0, 2));
        mx1 = fmaxf(mx1, __shfl_xor_sync(0xffffffffu, mx1, 1));
        mx1 = fmaxf(mx1, __shfl_xor_sync(0xffffffffu, mx1, 2));
        float mn0 = fmaxf(m0, mx0), mn1 = fmaxf(m1, mx1);
        float sc0 = __expf(m0 - mn0), sc1 = __expf(m1 - mn1);
        m0 = mn0; m1 = mn1;
        l0 *= sc0; l1 *= sc1;
        #pragma unroll
        for (int j = 0; j < 8; j++) {
            O[j][0] *= sc0; O[j][1] *= sc0;
            O[j][2] *= sc1; O[j][3] *= sc1;
        }
        #pragma unroll
        for (int j = 0; j < 8; j++) {
            S[j][0] = __expf(S[j][0] - mn0);
            S[j][1] = __expf(S[j][1] - mn0);
            S[j][2] = __expf(S[j][2] - mn1);
            S[j][3] = __expf(S[j][3] - mn1);
            l0 += S[j][0] + S[j][1];
            l1 += S[j][2] + S[j][3];
        }

        // --- pack P into A-fragments (hi/lo) ---
        uint32_t aPh[4][4], aPl[4][4];
        #pragma unroll
        for (int t = 0; t < 4; t++) {
            #pragma unroll
            for (int u = 0; u < 2; u++) {          // u=0 -> ntile 2t (regs 0,1), u=1 -> 2t+1 (regs 2,3)
                float* s = S[2 * t + u];
                __nv_bfloat162 h01 = __floats2bfloat162_rn(s[0], s[1]);
                __nv_bfloat162 h23 = __floats2bfloat162_rn(s[2], s[3]);
                float r0 = s[0] - __bfloat162float(h01.x);
                float r1 = s[1] - __bfloat162float(h01.y);
                float r2 = s[2] - __bfloat162float(h23.x);
                float r3 = s[3] - __bfloat162float(h23.y);
                __nv_bfloat162 l01 = __floats2bfloat162_rn(r0, r1);
                __nv_bfloat162 l23 = __floats2bfloat162_rn(r2, r3);
                aPh[t][2 * u]     = *(uint32_t*)&h01;
                aPh[t][2 * u + 1] = *(uint32_t*)&h23;
                aPl[t][2 * u]     = *(uint32_t*)&l01;
                aPl[t][2 * u + 1] = *(uint32_t*)&l23;
            }
        }

        // --- O += P . V (3-term split), V B-frags via ldmatrix.trans ---
        #pragma unroll
        for (int t = 0; t < 4; t++) {              // kpos chunks of 16
            uint32_t rowOff = (t * 16 + (lane & 15)) * FROWB + (lane >> 4) * 16;
            #pragma unroll
            for (int g = 0; g < 4; g++) {          // d ntile pairs
                uint32_t off = rowOff + g * 32;
                uint32_t vh_[4], vl_[4];
                ldsm_x4_t(vh_, uVh_ + off);
                ldsm_x4_t(vl_, uVl_ + off);
                mma_bf16(O[2 * g],     aPh[t], vh_);
                mma_bf16(O[2 * g + 1], aPh[t], vh_ + 2);
                mma_bf16(O[2 * g],     aPh[t], vl_);
                mma_bf16(O[2 * g + 1], aPh[t], vl_ + 2);
                mma_bf16(O[2 * g],     aPl[t], vh_);
                mma_bf16(O[2 * g + 1], aPl[t], vh_ + 2);
            }
        }

        __syncthreads();
        if (kt + 2 < 32) issue(kt + 2, stage);
    }

    // --- finalize ---
    l0 += __shfl_xor_sync(0xffffffffu, l0, 1);
    l0 += __shfl_xor_sync(0xffffffffu, l0, 2);
    l1 += __shfl_xor_sync(0xffffffffu, l1, 1);
    l1 += __shfl_xor_sync(0xffffffffu, l1, 2);
    float inv0 = 1.0f / l0, inv1 = 1.0f / l1;

    const int b = bh >> 4, h = bh & 15;
    const int qr = qt * 128 + w * 16 + (lane >> 2);
    #pragma unroll
    for (int j = 0; j < 8; j++) {
        int col = h * HDIM + j * 8 + colOff;
        {
            float v0 = O[j][0] * inv0, v1 = O[j][1] * inv0;
            __nv_bfloat16 h0 = __float2bfloat16(v0), h1 = __float2bfloat16(v1);
            __nv_bfloat16 e0 = __float2bfloat16(v0 - __bfloat162float(h0));
            __nv_bfloat16 e1 = __float2bfloat16(v1 - __bfloat162float(h1));
            size_t o = (size_t)(b * SEQ + qr) * DMODEL + col;
            *(__nv_bfloat162*)(ctxh + o) = __halves2bfloat162(h0, h1);
            *(__nv_bfloat162*)(ctxl + o) = __halves2bfloat162(e0, e1);
        }
        {
            float v0 = O[j][2] * inv1, v1 = O[j][3] * inv1;
            __nv_bfloat16 h0 = __float2bfloat16(v0), h1 = __float2bfloat16(v1);
            __nv_bfloat16 e0 = __float2bfloat16(v0 - __bfloat162float(h0));
            __nv_bfloat16 e1 = __float2bfloat16(v1 - __bfloat162float(h1));
            size_t o = (size_t)(b * SEQ + qr + 8) * DMODEL + col;
            *(__nv_bfloat162*)(ctxh + o) = __halves2bfloat162(h0, h1);
            *(__nv_bfloat162*)(ctxl + o) = __halves2bfloat162(e0, e1);
        }
    }
}

// ---------------------------------------------------------------------------
// Launch
// ---------------------------------------------------------------------------
extern "C" void kernel_launch(void* const* d_in, const int* in_sizes, int n_in,
                              void* d_out, int out_size)
{
    const float* x    = (const float*)d_in[0];
    const int*   mask = (const int*)  d_in[1];
    const float* W[4] = { (const float*)d_in[2], (const float*)d_in[4],
                          (const float*)d_in[6], (const float*)d_in[8] };
    const float* bq   = (const float*)d_in[3];
    const float* bk   = (const float*)d_in[5];
    const float* bv   = (const float*)d_in[7];
    const float* bo   = (const float*)d_in[9];
    float* out = (float*)d_out;

    __nv_bfloat16 *xh, *xl, *wth, *wtl, *qh, *ql, *kh, *kl, *vh, *vl, *cxh, *cxl;
    cudaGetSymbolAddress((void**)&xh,  g_xh);
    cudaGetSymbolAddress((void**)&xl,  g_xl);
    cudaGetSymbolAddress((void**)&wth, g_WTh);
    cudaGetSymbolAddress((void**)&wtl, g_WTl);
    cudaGetSymbolAddress((void**)&qh,  g_Qh);
    cudaGetSymbolAddress((void**)&ql,  g_Ql);
    cudaGetSymbolAddress((void**)&kh,  g_Kh);
    cudaGetSymbolAddress((void**)&kl,  g_Kl);
    cudaGetSymbolAddress((void**)&vh,  g_Vh);
    cudaGetSymbolAddress((void**)&vl,  g_Vl);
    cudaGetSymbolAddress((void**)&cxh, g_ctxh);
    cudaGetSymbolAddress((void**)&cxl, g_ctxl);

    cudaFuncSetAttribute(flash_mma, cudaFuncAttributeMaxDynamicSharedMemorySize, FLASH_SMEM);

    split_f32<<<(MTOT * DMODEL) / 256, 256>>>(x, xh, xl, MTOT * DMODEL);
    for (int i = 0; i < 4; i++)
        transpose_split<<<dim3(32, 32), dim3(32, 8)>>>(W[i],
            wth + (size_t)i * DMODEL * DMODEL, wtl + (size_t)i * DMODEL * DMODEL);

    dim3 mmGrid(DMODEL / 128, MTOT / 128);   // (8, 32)
    mm_mma<<<mmGrid, 256>>>(xh, xl, wth + 0 * (size_t)DMODEL * DMODEL,
                            wtl + 0 * (size_t)DMODEL * DMODEL, bq, nullptr, qh, ql, 1);
    mm_mma<<<mmGrid, 256>>>(xh, xl, wth + 1 * (size_t)DMODEL * DMODEL,
                            wtl + 1 * (size_t)DMODEL * DMODEL, bk, nullptr, kh, kl, 1);
    mm_mma<<<mmGrid, 256>>>(xh, xl, wth + 2 * (size_t)DMODEL * DMODEL,
                            wtl + 2 * (size_t)DMODEL * DMODEL, bv, nullptr, vh, vl, 1);

    flash_mma<<<dim3(SEQ / 128, BATCH * NHEADS), 256, FLASH_SMEM>>>(
        qh, ql, kh, kl, vh, vl, mask, cxh, cxl);

    mm_mma<<<mmGrid, 256>>>(cxh, cxl, wth + 3 * (size_t)DMODEL * DMODEL,
                            wtl + 3 * (size_t)DMODEL * DMODEL, bo, out, nullptr, nullptr, 0);
}

// round 5
// speedup vs baseline: 2.3612x; 1.0103x over previous
#include <cuda_runtime.h>
#include <cuda_bf16.h>
#include <cstdint>

#define BATCH 2
#define SEQ 2048
#define DMODEL 1024
#define NHEADS 16
#define HDIM 64
#define MTOT (BATCH * SEQ)          // 4096

// ---------------------------------------------------------------------------
// Scratch (static device globals)
// ---------------------------------------------------------------------------
__device__ __align__(16) __nv_bfloat16 g_xh[MTOT * DMODEL];
__device__ __align__(16) __nv_bfloat16 g_xl[MTOT * DMODEL];
__device__ __align__(16) __nv_bfloat16 g_WTh[4][DMODEL * DMODEL];
__device__ __align__(16) __nv_bfloat16 g_WTl[4][DMODEL * DMODEL];
__device__ __align__(16) float g_bias3[3 * DMODEL];
__device__ __align__(16) __nv_bfloat16 g_Qh[BATCH * NHEADS * SEQ * HDIM];  // [B,H,S,Dh]
__device__ __align__(16) __nv_bfloat16 g_Ql[BATCH * NHEADS * SEQ * HDIM];
__device__ __align__(16) __nv_bfloat16 g_Kh[BATCH * NHEADS * SEQ * HDIM];
__device__ __align__(16) __nv_bfloat16 g_Kl[BATCH * NHEADS * SEQ * HDIM];
__device__ __align__(16) __nv_bfloat16 g_Vh[BATCH * NHEADS * SEQ * HDIM];
__device__ __align__(16) __nv_bfloat16 g_Vl[BATCH * NHEADS * SEQ * HDIM];
__device__ __align__(16) __nv_bfloat16 g_ctxh[MTOT * DMODEL];
__device__ __align__(16) __nv_bfloat16 g_ctxl[MTOT * DMODEL];

// ---------------------------------------------------------------------------
// Helpers (portable PTX, compiles at compute_103)
// ---------------------------------------------------------------------------
__device__ __forceinline__ uint32_t smem_u32(const void* p) {
    uint32_t a;
    asm("{ .reg .u64 t; cvta.to.shared.u64 t, %1; cvt.u32.u64 %0, t; }" : "=r"(a) : "l"(p));
    return a;
}
__device__ __forceinline__ void ldsm_x4(uint32_t* r, uint32_t addr) {
    asm volatile("ldmatrix.sync.aligned.m8n8.x4.shared.b16 {%0,%1,%2,%3}, [%4];"
        : "=r"(r[0]), "=r"(r[1]), "=r"(r[2]), "=r"(r[3]) : "r"(addr));
}
__device__ __forceinline__ void ldsm_x4_t(uint32_t* r, uint32_t addr) {
    asm volatile("ldmatrix.sync.aligned.m8n8.x4.trans.shared.b16 {%0,%1,%2,%3}, [%4];"
        : "=r"(r[0]), "=r"(r[1]), "=r"(r[2]), "=r"(r[3]) : "r"(addr));
}
__device__ __forceinline__ void mma_bf16(float* d, const uint32_t* a, const uint32_t* b) {
    asm volatile("mma.sync.aligned.m16n8k16.row.col.f32.bf16.bf16.f32 "
        "{%0,%1,%2,%3}, {%4,%5,%6,%7}, {%8,%9}, {%0,%1,%2,%3};"
        : "+f"(d[0]), "+f"(d[1]), "+f"(d[2]), "+f"(d[3])
        : "r"(a[0]), "r"(a[1]), "r"(a[2]), "r"(a[3]), "r"(b[0]), "r"(b[1]));
}
#define CP_ASYNC16(dst_u32, src_gptr) \
    asm volatile("cp.async.cg.shared.global [%0], [%1], 16;" \
        :: "r"(dst_u32), "l"(__cvta_generic_to_global(src_gptr)) : "memory")
#define CP_COMMIT() asm volatile("cp.async.commit_group;" ::: "memory")
#define CP_WAIT1()  asm volatile("cp.async.wait_group 1;" ::: "memory")
#define CP_WAIT0()  asm volatile("cp.async.wait_group 0;" ::: "memory")

// ---------------------------------------------------------------------------
// Prep kernels
// ---------------------------------------------------------------------------
__global__ void split_f32(const float* __restrict__ X, __nv_bfloat16* __restrict__ Xh,
                          __nv_bfloat16* __restrict__ Xl, int n)
{
    int i = blockIdx.x * blockDim.x + threadIdx.x;
    if (i < n) {
        float v = X[i];
        __nv_bfloat16 h = __float2bfloat16(v);
        Xh[i] = h;
        Xl[i] = __float2bfloat16(v - __bfloat162float(h));
    }
}

__global__ void transpose_split4(const float* __restrict__ W0, const float* __restrict__ W1,
                                 const float* __restrict__ W2, const float* __restrict__ W3,
                                 __nv_bfloat16* __restrict__ ThBase, __nv_bfloat16* __restrict__ TlBase)
{
    __shared__ float t[32][33];
    const int z = blockIdx.z;
    const float* W = (z == 0) ? W0 : (z == 1) ? W1 : (z == 2) ? W2 : W3;
    __nv_bfloat16* Th = ThBase + (size_t)z * DMODEL * DMODEL;
    __nv_bfloat16* Tl = TlBase + (size_t)z * DMODEL * DMODEL;
    int bx = blockIdx.x * 32;
    int by = blockIdx.y * 32;
    int tx = threadIdx.x, ty = threadIdx.y;
    #pragma unroll
    for (int i = 0; i < 4; i++)
        t[ty + i * 8][tx] = W[(size_t)(by + ty + i * 8) * DMODEL + bx + tx];
    __syncthreads();
    #pragma unroll
    for (int i = 0; i < 4; i++) {
        float v = t[tx][ty + i * 8];
        size_t o = (size_t)(bx + ty + i * 8) * DMODEL + by + tx;
        __nv_bfloat16 h = __float2bfloat16(v);
        Th[o] = h;
        Tl[o] = __float2bfloat16(v - __bfloat162float(h));
    }
}

__global__ void concat_bias(const float* __restrict__ a, const float* __restrict__ b,
                            const float* __restrict__ c, float* __restrict__ o)
{
    int i = blockIdx.x * blockDim.x + threadIdx.x;
    if (i < DMODEL) { o[i] = a[i]; o[i + DMODEL] = b[i]; o[i + 2 * DMODEL] = c[i]; }
}

// ---------------------------------------------------------------------------
// HMMA GEMM v2: cp.async 2-stage pipeline, 2 CTA/SM target.
// C[4096, N] = A @ BT^T + bias.   N=3072 (QKV fused) or 1024 (O proj).
// mode=1: bf16 hi/lo out, [B,H,S,Dh] per the selected third of N.
// mode=0: fp32 out row-major.
// ---------------------------------------------------------------------------
#define MKS 40                              // bf16 per smem row (32 data + 8 pad)
#define ARRB (128 * MKS * 2)                // 10240 B per array
#define MM2_SMEM (2 * 4 * ARRB)             // 81920 B

__global__ __launch_bounds__(256, 2)
void mm2(const __nv_bfloat16* __restrict__ Ah, const __nv_bfloat16* __restrict__ Al,
         const __nv_bfloat16* __restrict__ BTh, const __nv_bfloat16* __restrict__ BTl,
         const float* __restrict__ bias, int mode, float* __restrict__ Cf,
         __nv_bfloat16* __restrict__ oQh, __nv_bfloat16* __restrict__ oQl,
         __nv_bfloat16* __restrict__ oKh, __nv_bfloat16* __restrict__ oKl,
         __nv_bfloat16* __restrict__ oVh, __nv_bfloat16* __restrict__ oVl)
{
    extern __shared__ char sm[];
    const uint32_t sb = smem_u32(sm);

    const int tid = threadIdx.x;
    const int wid = tid >> 5;
    const int lane = tid & 31;
    const int wm = wid & 3;
    const int wn = wid >> 2;
    const int bm = blockIdx.y * 128;
    const int bn = blockIdx.x * 128;

    const int wsel = bn >> 10;
    const __nv_bfloat16* Bh = BTh + (size_t)wsel * DMODEL * DMODEL;
    const __nv_bfloat16* Bl = BTl + (size_t)wsel * DMODEL * DMODEL;
    const int rB = bn & 1023;

    // per-thread load coords: 2 16B units per array
    int rr[2], sg[2];
    #pragma unroll
    for (int u = 0; u < 2; u++) { int lin = tid * 2 + u; rr[u] = lin >> 2; sg[u] = lin & 3; }

    auto issue = [&](int c, int st) {
        const int k0 = c * 32;
        #pragma unroll
        for (int u = 0; u < 2; u++) {
            uint32_t so = (rr[u] * MKS + sg[u] * 8) * 2;
            uint32_t dst = sb + st * 4 * ARRB + so;
            size_t ga = (size_t)(bm + rr[u]) * DMODEL + k0 + sg[u] * 8;
            size_t gb = (size_t)(rB + rr[u]) * DMODEL + k0 + sg[u] * 8;
            CP_ASYNC16(dst + 0 * ARRB, Ah + ga);
            CP_ASYNC16(dst + 1 * ARRB, Al + ga);
            CP_ASYNC16(dst + 2 * ARRB, Bh + gb);
            CP_ASYNC16(dst + 3 * ARRB, Bl + gb);
        }
        CP_COMMIT();
    };

    issue(0, 0);
    issue(1, 1);

    float acc[2][8][4];
    #pragma unroll
    for (int mi = 0; mi < 2; mi++)
        #pragma unroll
        for (int ni = 0; ni < 8; ni++)
            #pragma unroll
            for (int e = 0; e < 4; e++) acc[mi][ni][e] = 0.0f;

    const int aRow = wm * 32 + (lane & 15);
    const int aK   = (lane >> 4) * 8;
    const int bRow = wn * 64 + ((lane >> 4) & 1) * 8 + (lane & 7);
    const int bK   = ((lane >> 3) & 1) * 8;

    const int NCH = DMODEL / 32;   // 32
    for (int c = 0; c < NCH; c++) {
        const int st = c & 1;
        if (c + 1 < NCH) { CP_WAIT1(); } else { CP_WAIT0(); }
        __syncthreads();

        const uint32_t uAh = sb + st * 4 * ARRB + 0 * ARRB;
        const uint32_t uAl = sb + st * 4 * ARRB + 1 * ARRB;
        const uint32_t uBh = sb + st * 4 * ARRB + 2 * ARRB;
        const uint32_t uBl = sb + st * 4 * ARRB + 3 * ARRB;

        #pragma unroll
        for (int s = 0; s < 2; s++) {
            uint32_t aH[2][4], aL[2][4];
            #pragma unroll
            for (int mi = 0; mi < 2; mi++) {
                uint32_t off = ((aRow + mi * 16) * MKS + s * 16 + aK) * 2;
                ldsm_x4(aH[mi], uAh + off);
                ldsm_x4(aL[mi], uAl + off);
            }
            #pragma unroll
            for (int g = 0; g < 4; g++) {
                uint32_t off = ((bRow + g * 16) * MKS + s * 16 + bK) * 2;
                uint32_t bH[4], bL[4];
                ldsm_x4(bH, uBh + off);
                ldsm_x4(bL, uBl + off);
                #pragma unroll
                for (int mi = 0; mi < 2; mi++) {
                    mma_bf16(acc[mi][2 * g],     aH[mi], bH);
                    mma_bf16(acc[mi][2 * g + 1], aH[mi], bH + 2);
                    mma_bf16(acc[mi][2 * g],     aH[mi], bL);
                    mma_bf16(acc[mi][2 * g + 1], aH[mi], bL + 2);
                    mma_bf16(acc[mi][2 * g],     aL[mi], bH);
                    mma_bf16(acc[mi][2 * g + 1], aL[mi], bH + 2);
                }
            }
        }

        __syncthreads();
        if (c + 2 < NCH) issue(c + 2, st);
    }

    // Epilogue
    const int rBase = bm + wm * 32 + (lane >> 2);
    const int cBase = bn + wn * 64 + (lane & 3) * 2;
    __nv_bfloat16 *oh = nullptr, *ol = nullptr;
    if (mode) {
        oh = (wsel == 0) ? oQh : (wsel == 1) ? oKh : oVh;
        ol = (wsel == 0) ? oQl : (wsel == 1) ? oKl : oVl;
    }
    #pragma unroll
    for (int mi = 0; mi < 2; mi++) {
        #pragma unroll
        for (int ni = 0; ni < 8; ni++) {
            int col = cBase + ni * 8;
            float b0 = bias[col], b1 = bias[col + 1];
            #pragma unroll
            for (int half = 0; half < 2; half++) {
                int m = rBase + mi * 16 + half * 8;
                float v0 = acc[mi][ni][half * 2 + 0] + b0;
                float v1 = acc[mi][ni][half * 2 + 1] + b1;
                if (mode) {
                    int n1 = col & 1023;
                    int b = m >> 11, s = m & 2047;
                    int h = n1 >> 6, d = n1 & 63;
                    size_t o = ((size_t)((b << 4) + h) * SEQ + s) * HDIM + d;
                    __nv_bfloat16 h0 = __float2bfloat16(v0);
                    __nv_bfloat16 h1 = __float2bfloat16(v1);
                    __nv_bfloat16 l0 = __float2bfloat16(v0 - __bfloat162float(h0));
                    __nv_bfloat16 l1 = __float2bfloat16(v1 - __bfloat162float(h1));
                    *(__nv_bfloat162*)(oh + o) = __halves2bfloat162(h0, h1);
                    *(__nv_bfloat162*)(ol + o) = __halves2bfloat162(l0, l1);
                } else {
                    float* dst = Cf + (size_t)m * DMODEL + col;
                    dst[0] = v0; dst[1] = v1;
                }
            }
        }
    }
}

// ---------------------------------------------------------------------------
// Flash attention on HMMA (as Round 4, exp -> exp2 domain)
// ---------------------------------------------------------------------------
#define FSTR 72
#define FROWB (FSTR * 2)
#define FQ_BYTES (128 * FSTR * 2)
#define FT_BYTES (64 * FSTR * 2)
#define FLASH_SMEM (2 * FQ_BYTES + 2 * 4 * FT_BYTES)  // 110592
#define SCALE_LOG2E 0.18033688011112042f               // 0.125 * log2(e)

__global__ __launch_bounds__(256, 1)
void flash_mma(const __nv_bfloat16* __restrict__ Qh, const __nv_bfloat16* __restrict__ Ql,
               const __nv_bfloat16* __restrict__ Kh, const __nv_bfloat16* __restrict__ Kl,
               const __nv_bfloat16* __restrict__ Vh, const __nv_bfloat16* __restrict__ Vl,
               const int* __restrict__ mask,
               __nv_bfloat16* __restrict__ ctxh, __nv_bfloat16* __restrict__ ctxl)
{
    extern __shared__ char sm[];
    __nv_bfloat16* sQh = (__nv_bfloat16*)sm;
    __nv_bfloat16* sQl = sQh + 128 * FSTR;
    char* sKV = sm + 2 * FQ_BYTES;

    const int tid = threadIdx.x;
    const int lane = tid & 31;
    const int w = tid >> 5;
    const int qt = blockIdx.x;
    const int bh = blockIdx.y;
    const size_t base = (size_t)bh * SEQ * HDIM;

    #pragma unroll
    for (int i = 0; i < 4; i++) {
        int lin = tid + i * 256;
        int r = lin >> 3, c = lin & 7;
        *(uint4*)&sQh[r * FSTR + c * 8] = *(const uint4*)&Qh[base + (size_t)(qt * 128 + r) * HDIM + c * 8];
        *(uint4*)&sQl[r * FSTR + c * 8] = *(const uint4*)&Ql[base + (size_t)(qt * 128 + r) * HDIM + c * 8];
    }

    const uint32_t uKV = smem_u32(sKV);
    const __nv_bfloat16* srcs[4] = { Kh, Kl, Vh, Vl };

    auto issue = [&](int kt, int stage) {
        #pragma unroll
        for (int t = 0; t < 4; t++) {
            #pragma unroll
            for (int u = 0; u < 2; u++) {
                int lin = tid * 2 + u;
                int r = lin >> 3, c = lin & 7;
                uint32_t dst = uKV + (stage * 4 + t) * FT_BYTES + r * FROWB + c * 16;
                const __nv_bfloat16* src = srcs[t] + base + (size_t)(kt * 64 + r) * HDIM + c * 8;
                CP_ASYNC16(dst, src);
            }
        }
        CP_COMMIT();
    };

    issue(0, 0);
    issue(1, 1);

    __syncthreads();

    uint32_t qhf[4][4], qlf[4][4];
    const uint32_t uQh = smem_u32(sQh), uQl = smem_u32(sQl);
    #pragma unroll
    for (int kch = 0; kch < 4; kch++) {
        uint32_t off = (w * 16 + (lane & 15)) * FROWB + (kch * 16 + (lane >> 4) * 8) * 2;
        ldsm_x4(qhf[kch], uQh + off);
        ldsm_x4(qlf[kch], uQl + off);
    }

    float O[8][4];
    #pragma unroll
    for (int j = 0; j < 8; j++)
        #pragma unroll
        for (int e = 0; e < 4; e++) O[j][e] = 0.0f;
    float m0 = -1e30f, m1 = -1e30f, l0 = 0.0f, l1 = 0.0f;

    const int q0 = qt * 128 + w * 16 + (lane >> 2);
    const int colOff = 2 * (lane & 3);

    for (int kt = 0; kt < 32; kt++) {
        const int stage = kt & 1;
        if (kt + 1 < 32) { CP_WAIT1(); } else { CP_WAIT0(); }
        __syncthreads();

        const uint32_t uKh_ = uKV + (stage * 4 + 0) * FT_BYTES;
        const uint32_t uKl_ = uKV + (stage * 4 + 1) * FT_BYTES;
        const uint32_t uVh_ = uKV + (stage * 4 + 2) * FT_BYTES;
        const uint32_t uVl_ = uKV + (stage * 4 + 3) * FT_BYTES;

        float S[8][4];
        #pragma unroll
        for (int j = 0; j < 8; j++)
            #pragma unroll
            for (int e = 0; e < 4; e++) S[j][e] = 0.0f;

        const int rowN = ((lane >> 4) & 1) * 8 + (lane & 7);
        const int bKo  = ((lane >> 3) & 1) * 16;
        #pragma unroll
        for (int g = 0; g < 4; g++) {
            #pragma unroll
            for (int kch = 0; kch < 4; kch++) {
                uint32_t off = (g * 16 + rowN) * FROWB + kch * 32 + bKo;
                uint32_t bh_[4], bl_[4];
                ldsm_x4(bh_, uKh_ + off);
                ldsm_x4(bl_, uKl_ + off);
                mma_bf16(S[2 * g],     qhf[kch], bh_);
                mma_bf16(S[2 * g + 1], qhf[kch], bh_ + 2);
                mma_bf16(S[2 * g],     qhf[kch], bl_);
                mma_bf16(S[2 * g + 1], qhf[kch], bl_ + 2);
                mma_bf16(S[2 * g],     qlf[kch], bh_);
                mma_bf16(S[2 * g + 1], qlf[kch], bh_ + 2);
            }
        }

        #pragma unroll
        for (int j = 0; j < 8; j++) {
            int kc = kt * 64 + j * 8 + colOff;
            int2 mA = *(const int2*)&mask[(size_t)q0 * SEQ + kc];
            int2 mB = *(const int2*)&mask[(size_t)(q0 + 8) * SEQ + kc];
            S[j][0] = mA.x ? S[j][0] * SCALE_LOG2E : -1e9f;
            S[j][1] = mA.y ? S[j][1] * SCALE_LOG2E : -1e9f;
            S[j][2] = mB.x ? S[j][2] * SCALE_LOG2E : -1e9f;
            S[j][3] = mB.y ? S[j][3] * SCALE_LOG2E : -1e9f;
        }

        float mx0 = -1e30f, mx1 = -1e30f;
        #pragma unroll
        for (int j = 0; j < 8; j++) {
            mx0 = fmaxf(mx0, fmaxf(S[j][0], S[j][1]));
            mx1 = fmaxf(mx1, fmaxf(S[j][2], S[j][3]));
        }
        mx0 = fmaxf(mx0, __shfl_xor_sync(0xffffffffu, mx0, 1));
        mx0 = fmaxf(mx0, __shfl_xor_sync(0xffffffffu, mx0, 2));
        mx1 = fmaxf(mx1, __shfl_xor_sync(0xffffffffu, mx1, 1));
        mx1 = fmaxf(mx1, __shfl_xor_sync(0xffffffffu, mx1, 2));
        float mn0 = fmaxf(m0, mx0), mn1 = fmaxf(m1, mx1);
        float sc0 = exp2f(m0 - mn0), sc1 = exp2f(m1 - mn1);
        m0 = mn0; m1 = mn1;
        l0 *= sc0; l1 *= sc1;
        #pragma unroll
        for (int j = 0; j < 8; j++) {
            O[j][0] *= sc0; O[j][1] *= sc0;
            O[j][2] *= sc1; O[j][3] *= sc1;
        }
        #pragma unroll
        for (int j = 0; j < 8; j++) {
            S[j][0] = exp2f(S[j][0] - mn0);
            S[j][1] = exp2f(S[j][1] - mn0);
            S[j][2] = exp2f(S[j][2] - mn1);
            S[j][3] = exp2f(S[j][3] - mn1);
            l0 += S[j][0] + S[j][1];
            l1 += S[j][2] + S[j][3];
        }

        uint32_t aPh[4][4], aPl[4][4];
        #pragma unroll
        for (int t = 0; t < 4; t++) {
            #pragma unroll
            for (int u = 0; u < 2; u++) {
                float* s = S[2 * t + u];
                __nv_bfloat162 h01 = __floats2bfloat162_rn(s[0], s[1]);
                __nv_bfloat162 h23 = __floats2bfloat162_rn(s[2], s[3]);
                float r0 = s[0] - __bfloat162float(h01.x);
                float r1 = s[1] - __bfloat162float(h01.y);
                float r2 = s[2] - __bfloat162float(h23.x);
                float r3 = s[3] - __bfloat162float(h23.y);
                __nv_bfloat162 l01 = __floats2bfloat162_rn(r0, r1);
                __nv_bfloat162 l23 = __floats2bfloat162_rn(r2, r3);
                aPh[t][2 * u]     = *(uint32_t*)&h01;
                aPh[t][2 * u + 1] = *(uint32_t*)&h23;
                aPl[t][2 * u]     = *(uint32_t*)&l01;
                aPl[t][2 * u + 1] = *(uint32_t*)&l23;
            }
        }

        #pragma unroll
        for (int t = 0; t < 4; t++) {
            uint32_t rowOff = (t * 16 + (lane & 15)) * FROWB + (lane >> 4) * 16;
            #pragma unroll
            for (int g = 0; g < 4; g++) {
                uint32_t off = rowOff + g * 32;
                uint32_t vh_[4], vl_[4];
                ldsm_x4_t(vh_, uVh_ + off);
                ldsm_x4_t(vl_, uVl_ + off);
                mma_bf16(O[2 * g],     aPh[t], vh_);
                mma_bf16(O[2 * g + 1], aPh[t], vh_ + 2);
                mma_bf16(O[2 * g],     aPh[t], vl_);
                mma_bf16(O[2 * g + 1], aPh[t], vl_ + 2);
                mma_bf16(O[2 * g],     aPl[t], vh_);
                mma_bf16(O[2 * g + 1], aPl[t], vh_ + 2);
            }
        }

        __syncthreads();
        if (kt + 2 < 32) issue(kt + 2, stage);
    }

    l0 += __shfl_xor_sync(0xffffffffu, l0, 1);
    l0 += __shfl_xor_sync(0xffffffffu, l0, 2);
    l1 += __shfl_xor_sync(0xffffffffu, l1, 1);
    l1 += __shfl_xor_sync(0xffffffffu, l1, 2);
    float inv0 = 1.0f / l0, inv1 = 1.0f / l1;

    const int b = bh >> 4, h = bh & 15;
    const int qr = qt * 128 + w * 16 + (lane >> 2);
    #pragma unroll
    for (int j = 0; j < 8; j++) {
        int col = h * HDIM + j * 8 + colOff;
        {
            float v0 = O[j][0] * inv0, v1 = O[j][1] * inv0;
            __nv_bfloat16 h0 = __float2bfloat16(v0), h1 = __float2bfloat16(v1);
            __nv_bfloat16 e0 = __float2bfloat16(v0 - __bfloat162float(h0));
            __nv_bfloat16 e1 = __float2bfloat16(v1 - __bfloat162float(h1));
            size_t o = (size_t)(b * SEQ + qr) * DMODEL + col;
            *(__nv_bfloat162*)(ctxh + o) = __halves2bfloat162(h0, h1);
            *(__nv_bfloat162*)(ctxl + o) = __halves2bfloat162(e0, e1);
        }
        {
            float v0 = O[j][2] * inv1, v1 = O[j][3] * inv1;
            __nv_bfloat16 h0 = __float2bfloat16(v0), h1 = __float2bfloat16(v1);
            __nv_bfloat16 e0 = __float2bfloat16(v0 - __bfloat162float(h0));
            __nv_bfloat16 e1 = __float2bfloat16(v1 - __bfloat162float(h1));
            size_t o = (size_t)(b * SEQ + qr + 8) * DMODEL + col;
            *(__nv_bfloat162*)(ctxh + o) = __halves2bfloat162(h0, h1);
            *(__nv_bfloat162*)(ctxl + o) = __halves2bfloat162(e0, e1);
        }
    }
}

// ---------------------------------------------------------------------------
// Launch
// ---------------------------------------------------------------------------
extern "C" void kernel_launch(void* const* d_in, const int* in_sizes, int n_in,
                              void* d_out, int out_size)
{
    const float* x    = (const float*)d_in[0];
    const int*   mask = (const int*)  d_in[1];
    const float* Wq   = (const float*)d_in[2];
    const float* bq   = (const float*)d_in[3];
    const float* Wk   = (const float*)d_in[4];
    const float* bk   = (const float*)d_in[5];
    const float* Wv   = (const float*)d_in[6];
    const float* bv   = (const float*)d_in[7];
    const float* Wo   = (const float*)d_in[8];
    const float* bo   = (const float*)d_in[9];
    float* out = (float*)d_out;

    __nv_bfloat16 *xh, *xl, *wth, *wtl, *qh, *ql, *kh, *kl, *vh, *vl, *cxh, *cxl;
    float* bias3;
    cudaGetSymbolAddress((void**)&xh,  g_xh);
    cudaGetSymbolAddress((void**)&xl,  g_xl);
    cudaGetSymbolAddress((void**)&wth, g_WTh);
    cudaGetSymbolAddress((void**)&wtl, g_WTl);
    cudaGetSymbolAddress((void**)&bias3, g_bias3);
    cudaGetSymbolAddress((void**)&qh,  g_Qh);
    cudaGetSymbolAddress((void**)&ql,  g_Ql);
    cudaGetSymbolAddress((void**)&kh,  g_Kh);
    cudaGetSymbolAddress((void**)&kl,  g_Kl);
    cudaGetSymbolAddress((void**)&vh,  g_Vh);
    cudaGetSymbolAddress((void**)&vl,  g_Vl);
    cudaGetSymbolAddress((void**)&cxh, g_ctxh);
    cudaGetSymbolAddress((void**)&cxl, g_ctxl);

    cudaFuncSetAttribute(mm2, cudaFuncAttributeMaxDynamicSharedMemorySize, MM2_SMEM);
    cudaFuncSetAttribute(flash_mma, cudaFuncAttributeMaxDynamicSharedMemorySize, FLASH_SMEM);

    split_f32<<<(MTOT * DMODEL) / 256, 256>>>(x, xh, xl, MTOT * DMODEL);
    transpose_split4<<<dim3(32, 32, 4), dim3(32, 8)>>>(Wq, Wk, Wv, Wo, wth, wtl);
    concat_bias<<<4, 256>>>(bq, bk, bv, bias3);

    // QKV fused: N = 3072
    mm2<<<dim3(24, 32), 256, MM2_SMEM>>>(xh, xl, wth, wtl, bias3, 1, nullptr,
                                         qh, ql, kh, kl, vh, vl);

    flash_mma<<<dim3(SEQ / 128, BATCH * NHEADS), 256, FLASH_SMEM>>>(
        qh, ql, kh, kl, vh, vl, mask, cxh, cxl);

    // O projection: N = 1024 (pass WT slot 3 directly)
    mm2<<<dim3(8, 32), 256, MM2_SMEM>>>(cxh, cxl,
        wth + 3 * (size_t)DMODEL * DMODEL, wtl + 3 * (size_t)DMODEL * DMODEL,
        bo, 0, out, nullptr, nullptr, nullptr, nullptr, nullptr, nullptr);
}